// round 1
// baseline (speedup 1.0000x reference)
#include <cuda_runtime.h>
#include <math.h>

// ScaleDotProductAttention with adjacency bias:
//   score = beta[h] * softmax(q k^T * scale + adj)   [H,N,N]
//   score[:, i, i] = alpha[h]                        (diagonal overwrite)
//   out = score @ v                                  [H,N,D]
//
// Exact algebraic identity used for the fast path:
//   out[h,n,:] = beta[h]*sum_m p_m v_m + (alpha[h] - beta[h]*p_n) * v[h,n,:]
// and when beta[h] == 0 this is EXACTLY out[h,n,:] = alpha[h]*v[h,n,:]
// (0 * softmax == 0 identically, independent of the softmax values).
//
// The kernel branches per-head on beta[h] read on-device (uniform within a
// block -> no divergence; deterministic: same inputs -> same work).
// The beta != 0 general path computes the full row softmax with deterministic
// tree reductions (no floating-point atomics) so output is bitwise stable
// across graph replays.

namespace {

constexpr int H_   = 8;
constexpr int N_   = 4096;
constexpr int D_   = 64;
constexpr int ROWS = 16;   // rows of the score matrix per block
constexpr int T_   = 256;  // threads per block

__global__ __launch_bounds__(T_) void attn_kernel(
    const float* __restrict__ q,
    const float* __restrict__ k,
    const float* __restrict__ v,
    const float* __restrict__ adj,
    const float* __restrict__ alpha,
    const float* __restrict__ beta,
    float* __restrict__ out)
{
    const int h    = blockIdx.y;
    const int row0 = blockIdx.x * ROWS;
    const float a  = alpha[h];
    const float b  = beta[h];

    const size_t tile_base = ((size_t)h * N_ + row0) * D_;

    if (b == 0.0f) {
        // ---- Exact fast path: out = alpha[h] * v ----
        // 16 rows * 64 floats = 1024 floats = 256 float4 -> one per thread.
        const float4* src = reinterpret_cast<const float4*>(v + tile_base);
        float4*       dst = reinterpret_cast<float4*>(out + tile_base);
        float4 val = src[threadIdx.x];
        val.x *= a; val.y *= a; val.z *= a; val.w *= a;
        dst[threadIdx.x] = val;
        return;
    }

    // ---- General path (correct for arbitrary alpha/beta) ----
    __shared__ float p[N_];          // 16 KB: one score row (then exp values)
    __shared__ float qrow[D_];
    __shared__ float red[T_ / 32];
    __shared__ float acc_s[4][D_];
    __shared__ float s_max, s_sum;

    const int tid  = threadIdx.x;
    const int lane = tid & 31;
    const int warp = tid >> 5;
    const float scale = rsqrtf((float)D_);

    const float* kb = k + (size_t)h * N_ * D_;
    const float* vb = v + (size_t)h * N_ * D_;

    for (int r = 0; r < ROWS; ++r) {
        const int n = row0 + r;

        if (tid < D_) qrow[tid] = q[((size_t)h * N_ + n) * D_ + tid];
        __syncthreads();

        const float* adjrow = adj + ((size_t)h * N_ + n) * N_;

        // Pass 1: scores -> p[], running max
        float lmax = -INFINITY;
        for (int m = tid; m < N_; m += T_) {
            const float* kp = kb + (size_t)m * D_;
            float s = 0.f;
            #pragma unroll
            for (int d = 0; d < D_; ++d) s = fmaf(qrow[d], kp[d], s);
            s = s * scale + adjrow[m];
            p[m] = s;
            lmax = fmaxf(lmax, s);
        }
        #pragma unroll
        for (int o = 16; o > 0; o >>= 1)
            lmax = fmaxf(lmax, __shfl_xor_sync(0xFFFFFFFFu, lmax, o));
        if (lane == 0) red[warp] = lmax;
        __syncthreads();
        if (warp == 0) {
            float m2 = (lane < T_ / 32) ? red[lane] : -INFINITY;
            #pragma unroll
            for (int o = 4; o > 0; o >>= 1)
                m2 = fmaxf(m2, __shfl_xor_sync(0xFFFFFFFFu, m2, o));
            if (lane == 0) s_max = m2;
        }
        __syncthreads();

        // Pass 2: exp + sum
        const float mx = s_max;
        float lsum = 0.f;
        for (int m = tid; m < N_; m += T_) {
            float e = expf(p[m] - mx);
            p[m] = e;
            lsum += e;
        }
        #pragma unroll
        for (int o = 16; o > 0; o >>= 1)
            lsum += __shfl_xor_sync(0xFFFFFFFFu, lsum, o);
        if (lane == 0) red[warp] = lsum;
        __syncthreads();
        if (warp == 0) {
            float t2 = (lane < T_ / 32) ? red[lane] : 0.f;
            #pragma unroll
            for (int o = 4; o > 0; o >>= 1)
                t2 += __shfl_xor_sync(0xFFFFFFFFu, t2, o);
            if (lane == 0) s_sum = t2;
        }
        __syncthreads();

        // Pass 3: acc[d] = sum_m p[m] * v[m][d]
        // Thread layout: dcol = tid % 64, group = tid / 64 (4 m-groups).
        // Deterministic cross-group reduce through smem (no atomics).
        const int dcol = tid & (D_ - 1);
        const int grp  = tid >> 6;
        float acc = 0.f;
        for (int m = grp; m < N_; m += 4)
            acc = fmaf(p[m], vb[(size_t)m * D_ + dcol], acc);
        acc_s[grp][dcol] = acc;
        __syncthreads();

        if (tid < D_) {
            const float tot =
                acc_s[0][tid] + acc_s[1][tid] + acc_s[2][tid] + acc_s[3][tid];
            const float inv = 1.0f / s_sum;
            const float vnd = vb[(size_t)n * D_ + tid];
            // full sum minus the m==n term's beta-weighted contribution,
            // diagonal replaced by alpha.
            const float o = b * inv * (tot - p[n] * vnd) + a * vnd;
            out[((size_t)h * N_ + n) * D_ + tid] = o;
        }
        __syncthreads();
    }
}

} // namespace

extern "C" void kernel_launch(void* const* d_in, const int* in_sizes, int n_in,
                              void* d_out, int out_size)
{
    const float* q     = (const float*)d_in[0];
    const float* k     = (const float*)d_in[1];
    const float* v     = (const float*)d_in[2];
    const float* adj   = (const float*)d_in[3];
    const float* alpha = (const float*)d_in[4];
    const float* beta  = (const float*)d_in[5];
    float* out = (float*)d_out;

    dim3 grid(N_ / ROWS, H_);
    attn_kernel<<<grid, T_>>>(q, k, v, adj, alpha, beta, out);
}